// round 8
// baseline (speedup 1.0000x reference)
#include <cuda_runtime.h>
#include <cstdint>

// MaSIF geodesic conv, GB300 sm_103a — crossbar-reduction round.
//
// Th[v][k][t] = E_v[((k+K0_v)&15) - t + 15]; E_v built with 4 exps/vertex.
// E stored reversed (EA[j] = E[30-j]) plus a one-shifted copy EB[j]=EA[j+1]
// at +32 in the same row, so any 4-run of descending E values becomes two
// 8B-aligned LDS.64 whose payloads are ready-packed f32x2 operands.
// Conv register-tiled 2 bins x 8 rotations per thread; desc reads are
// warp-uniform LDS.128 broadcasts shared across both bins.

#define NV    128
#define NBINS 80
#define EPSF  1e-5f

// smem float offsets
#define OFF_W     0          // 25600
#define OFF_A     25600      // 25 x 128
#define OFF_E     28800      // 128 x 66  (EA[0..30], EB at +32, stride 66)
#define OFF_ND    37248      // 25 x 256
#define OFF_DESC  43648      // 4 x 80 x 20 (stride-20 pad)
#define OFF_K0    50048      // 128 ints
#define OFF_MUR   50176      // 5
#define OFF_ISR   50184      // 5
#define SMEM_FLOATS 50192    // 200768 bytes

typedef unsigned long long u64;

__device__ __forceinline__ u64 pk2(float lo, float hi) {
    u64 r;
    asm("mov.b64 %0, {%1, %2};" : "=l"(r) : "f"(lo), "f"(hi));
    return r;
}
__device__ __forceinline__ void fma2(u64& d, u64 a, u64 b) {
    asm("fma.rn.f32x2 %0, %1, %2, %0;" : "+l"(d) : "l"(a), "l"(b));
}
__device__ __forceinline__ float2 upk2(u64 v) {
    float2 f;
    asm("mov.b64 {%0, %1}, %2;" : "=f"(f.x), "=f"(f.y) : "l"(v));
    return f;
}

__global__ __launch_bounds__(512, 1)
void masif_kernel(const float* __restrict__ rho,
                  const float* __restrict__ theta,
                  const float* __restrict__ feat,
                  const float* __restrict__ mask,
                  const float* __restrict__ mu_rho,
                  const float* __restrict__ sigma_rho,
                  const float* __restrict__ mu_theta,
                  const float* __restrict__ sigma_theta,
                  const float* __restrict__ W,
                  const float* __restrict__ bias,
                  float* __restrict__ out)
{
    extern __shared__ float sm[];
    float* s_W    = sm + OFF_W;
    float* s_A    = sm + OFF_A;
    float* s_E    = sm + OFF_E;
    float* s_ND   = sm + OFF_ND;
    float* s_desc = sm + OFF_DESC;
    int*   s_K0   = (int*)(sm + OFF_K0);
    float* s_mur  = sm + OFF_MUR;
    float* s_isr  = sm + OFF_ISR;

    const int tid = threadIdx.x;
    const int n   = blockIdx.x;
    const float two_pi = 6.2831855f;           // float32(2*pi)
    const float step   = two_pi / 16.0f;

    // ---- prologue: W via cp.async (waited before conv), small tables ----
    {
        const float4* Wg = (const float4*)W;
        uint32_t sbase = (uint32_t)__cvta_generic_to_shared(s_W);
        #pragma unroll 4
        for (int j = tid; j < 6400; j += 512) {
            uint32_t dst = sbase + j * 16;
            asm volatile("cp.async.ca.shared.global [%0], [%1], 16;\n"
                         :: "r"(dst), "l"(Wg + j));
        }
        asm volatile("cp.async.commit_group;\n" ::: "memory");
    }
    if (tid < 5) {
        s_mur[tid] = mu_rho[tid * 16];
        float s = sigma_rho[tid * 16];
        s_isr[tid] = 1.0f / (s * s + EPSF);
    }
    float st0 = sigma_theta[0];
    const float ist = 1.0f / (st0 * st0 + EPSF);
    __syncthreads();

    // ---- A build (warps 0..11) and E build (warps 12..15) in parallel ----
    if (tid < 384) {
        // A: cols 0..19 = rhoGauss*mask*feat_i, cols 20..24 = rhoGauss*mask
        for (int idx = tid; idx < 640; idx += 384) {
            int r = idx >> 7, v = idx & 127;
            float rv = rho[n * NV + v];
            float m  = mask[n * NV + v];
            float d  = rv - s_mur[r];
            float e  = __expf(-d * d * s_isr[r]) * m;
            s_A[(20 + r) * NV + v] = e;
            float4 f4 = ((const float4*)feat)[n * NV + v];
            s_A[(0 * 5 + r) * NV + v] = e * f4.x;
            s_A[(1 * 5 + r) * NV + v] = e * f4.y;
            s_A[(2 * 5 + r) * NV + v] = e * f4.z;
            s_A[(3 * 5 + r) * NV + v] = e * f4.w;
        }
    } else {
        // E tables (reversed + shifted copy): 4 exps per vertex
        int v = tid - 384;
        float th = theta[n * NV + v];
        float kf = floorf(th * (16.0f / two_pi));
        int K0 = (int)kf;
        if (K0 > 15) K0 = 15;
        if (K0 < 0)  K0 = 0;
        float u  = th - (float)K0 * step;
        float E0 = __expf(-ist * u * u);
        float q  = __expf(-ist * step * step);
        float q2 = q * q;
        float rr = __expf(-2.0f * ist * u * step);
        float ri = __expf( 2.0f * ist * u * step);
        float* row = s_E + v * 66;
        // EA[x] = E[30-x]; EB[j] = EA[j+1] stored at row[32+j]
        row[15] = E0;  row[46] = E0;                 // EA[15], EB[14]
        float e = E0, mlt = rr * q;
        #pragma unroll
        for (int j = 1; j <= 15; j++) {              // E[15+j] -> EA[15-j]
            e *= mlt;
            row[15 - j] = e;
            if (j < 15) row[46 - j] = e;             // EB[14-j]
            mlt *= q2;
        }
        e = E0; mlt = ri * q;
        #pragma unroll
        for (int j = 1; j <= 15; j++) {              // E[15-j] -> EA[15+j]
            e *= mlt;
            row[15 + j] = e;
            row[46 + j] = e;                         // EB[14+j]
            mlt *= q2;
        }
        s_K0[v] = K0;
    }
    __syncthreads();

    // ---- ND matmul: (25 x 128) @ (128 x 256) -> s_ND[25][256], FFMA2 ----
    // 10 warps; warp pair owns 5 A-columns (broadcast loads); lane owns 4 kt.
    if (tid < 320) {
        int cg = tid >> 6;            // 0..4, warp-uniform
        int q  = tid & 63;
        int c0 = cg * 5, kt0 = q * 4;
        int kg   = q >> 2;            // shared by all 4 kt of this lane
        int aoff = 15 + 4 * (q & 3);  // a = aoff - m

        u64 acc2[5][2];
        #pragma unroll
        for (int c = 0; c < 5; c++) { acc2[c][0] = 0ull; acc2[c][1] = 0ull; }

        #pragma unroll 2
        for (int v = 0; v < NV; v += 4) {
            float a_s[5][4];
            #pragma unroll
            for (int c = 0; c < 5; c++) {
                float4 a4 = *(const float4*)&s_A[(c0 + c) * NV + v];
                a_s[c][0] = a4.x; a_s[c][1] = a4.y;
                a_s[c][2] = a4.z; a_s[c][3] = a4.w;
            }
            int4 k4 = *(const int4*)&s_K0[v];        // warp-uniform broadcast
            int kvals[4] = {k4.x, k4.y, k4.z, k4.w};
            #pragma unroll
            for (int jv = 0; jv < 4; jv++) {
                const float* row = s_E + (v + jv) * 66;
                int m = (kg + kvals[jv]) & 15;
                int a = aoff - m;                    // 0..27
                int off0 = a + ((a & 1) ? 31 : 0);   // even offset, EA or EB copy
                u64 tv01 = *(const u64*)&row[off0];      // (E[base], E[base-1])
                u64 tv23 = *(const u64*)&row[off0 + 2];  // (E[base-2], E[base-3])
                #pragma unroll
                for (int c = 0; c < 5; c++) {
                    u64 aa = pk2(a_s[c][jv], a_s[c][jv]);
                    fma2(acc2[c][0], aa, tv01);
                    fma2(acc2[c][1], aa, tv23);
                }
            }
        }
        #pragma unroll
        for (int c = 0; c < 5; c++) {
            float2 lo = upk2(acc2[c][0]);
            float2 hi = upk2(acc2[c][1]);
            float4 o;
            o.x = lo.x; o.y = lo.y; o.z = hi.x; o.w = hi.y;
            *(float4*)&s_ND[(c0 + c) * 256 + kt0] = o;
        }
    }
    __syncthreads();

    // ---- divide: shared denominators, 1 rcp per (b, k) ----
    if (tid < 320) {
        int kq = tid / 80;               // 0..3
        int b  = tid - kq * 80;          // 0..79
        int r  = b >> 4, t = b & 15;
        const float* Dp = s_ND + (20 + r) * 256 + t;
        float rc[4];
        #pragma unroll
        for (int kk = 0; kk < 4; kk++)
            rc[kk] = __fdividef(1.0f, Dp[(kq * 4 + kk) * 16] + EPSF);
        #pragma unroll
        for (int i = 0; i < 4; i++) {
            const float* Np = s_ND + (i * 5 + r) * 256 + t;
            float4 o;
            o.x = Np[(kq * 4 + 0) * 16] * rc[0];
            o.y = Np[(kq * 4 + 1) * 16] * rc[1];
            o.z = Np[(kq * 4 + 2) * 16] * rc[2];
            o.w = Np[(kq * 4 + 3) * 16] * rc[3];
            *(float4*)&s_desc[(i * NBINS + b) * 20 + kq * 4] = o;
        }
    }
    asm volatile("cp.async.wait_group 0;\n" ::: "memory");
    __syncthreads();

    // ---- conv + max over 16 rot + relu: 2 bins x 8 rotations per thread ----
    if (tid < 320) {
        int i   = tid / 80;
        int rem = tid - i * 80;
        int bg  = rem >> 1, kh = rem & 1;
        int b0  = bg * 2;

        float2 bv = *(const float2*)&bias[i * NBINS + b0];
        u64 accA[4], accB[4];
        u64 bA = pk2(bv.x, bv.x), bB = pk2(bv.y, bv.y);
        #pragma unroll
        for (int j = 0; j < 4; j++) { accA[j] = bA; accB[j] = bB; }

        const float* wptr = s_W + i * NBINS * NBINS + b0;
        const float* dptr = s_desc + i * NBINS * 20 + kh * 8;
        #pragma unroll 4
        for (int bp = 0; bp < NBINS; bp++) {
            float2 wv = *(const float2*)&wptr[bp * NBINS];
            ulonglong2 q0 = *(const ulonglong2*)&dptr[bp * 20];       // k0..k3
            ulonglong2 q1 = *(const ulonglong2*)&dptr[bp * 20 + 4];   // k4..k7
            u64 wa = pk2(wv.x, wv.x);
            u64 wb = pk2(wv.y, wv.y);
            fma2(accA[0], q0.x, wa); fma2(accA[1], q0.y, wa);
            fma2(accA[2], q1.x, wa); fma2(accA[3], q1.y, wa);
            fma2(accB[0], q0.x, wb); fma2(accB[1], q0.y, wb);
            fma2(accB[2], q1.x, wb); fma2(accB[3], q1.y, wb);
        }
        float mA = -3.4e38f, mB = -3.4e38f;
        #pragma unroll
        for (int j = 0; j < 4; j++) {
            float2 pa = upk2(accA[j]);
            float2 pb = upk2(accB[j]);
            mA = fmaxf(mA, fmaxf(pa.x, pa.y));
            mB = fmaxf(mB, fmaxf(pb.x, pb.y));
        }
        // combine the two rotation halves (partner thread = tid^1, same warp)
        float oA = __shfl_xor_sync(0xFFFFFFFFu, mA, 1);
        float oB = __shfl_xor_sync(0xFFFFFFFFu, mB, 1);
        mA = fmaxf(mA, oA);
        mB = fmaxf(mB, oB);
        if (kh == 0) {
            out[(n * 4 + i) * NBINS + b0]     = fmaxf(mA, 0.0f);
            out[(n * 4 + i) * NBINS + b0 + 1] = fmaxf(mB, 0.0f);
        }
    }
}

extern "C" void kernel_launch(void* const* d_in, const int* in_sizes, int n_in,
                              void* d_out, int out_size)
{
    const float* rho         = (const float*)d_in[0];
    const float* theta       = (const float*)d_in[1];
    const float* feat        = (const float*)d_in[2];
    const float* mask        = (const float*)d_in[3];
    const float* mu_rho      = (const float*)d_in[4];
    const float* sigma_rho   = (const float*)d_in[5];
    const float* mu_theta    = (const float*)d_in[6];
    const float* sigma_theta = (const float*)d_in[7];
    const float* W           = (const float*)d_in[8];
    const float* bias        = (const float*)d_in[9];
    float* out = (float*)d_out;

    const size_t smem_bytes = SMEM_FLOATS * sizeof(float);   // 200768
    cudaFuncSetAttribute(masif_kernel,
                         cudaFuncAttributeMaxDynamicSharedMemorySize,
                         (int)smem_bytes);

    masif_kernel<<<4096, 512, smem_bytes>>>(
        rho, theta, feat, mask, mu_rho, sigma_rho, mu_theta, sigma_theta,
        W, bias, out);
}

// round 9
// speedup vs baseline: 1.8971x; 1.8971x over previous
#include <cuda_runtime.h>
#include <cstdint>

// MaSIF geodesic conv, GB300 sm_103a — occupancy round.
// Base = round-4 kernel (346us, known good); W no longer staged in smem
// (conv reads it coalesced via L1/L2), freeing 100KB -> 2 CTAs/SM.
//
// Th[v][k][t] = E_v[((k+K0_v)&15) - t + 15]; E_v built with 4 exps/vertex.
// ND:   (25 x 128) @ (128 x 256) in smem, FFMA2 accumulators.
// conv: desc @ W_i + b_i, max over 16 rotations, relu.

#define NV    128
#define NBINS 80
#define EPSF  1e-5f

// smem float offsets (per-CTA total 81472 bytes -> 2 CTAs/SM)
#define OFF_A     0          // 25 x 128
#define OFF_E     3200       // 128 x 33 (pad: conflict-free build + gather)
#define OFF_ND    7424       // 25 x 256
#define OFF_DESC  13824      // 4 x 80 x 20 (stride-20 pad)
#define OFF_K0    20224      // 128 ints
#define OFF_MUR   20352      // 5
#define OFF_ISR   20360      // 5
#define SMEM_FLOATS 20368    // 81472 bytes

typedef unsigned long long u64;

__device__ __forceinline__ u64 pk2(float lo, float hi) {
    u64 r;
    asm("mov.b64 %0, {%1, %2};" : "=l"(r) : "f"(lo), "f"(hi));
    return r;
}
__device__ __forceinline__ void fma2(u64& d, u64 a, u64 b) {
    asm("fma.rn.f32x2 %0, %1, %2, %0;" : "+l"(d) : "l"(a), "l"(b));
}
__device__ __forceinline__ float2 upk2(u64 v) {
    float2 f;
    asm("mov.b64 {%0, %1}, %2;" : "=f"(f.x), "=f"(f.y) : "l"(v));
    return f;
}

__global__ __launch_bounds__(384, 2)
void masif_kernel(const float* __restrict__ rho,
                  const float* __restrict__ theta,
                  const float* __restrict__ feat,
                  const float* __restrict__ mask,
                  const float* __restrict__ mu_rho,
                  const float* __restrict__ sigma_rho,
                  const float* __restrict__ mu_theta,
                  const float* __restrict__ sigma_theta,
                  const float* __restrict__ W,
                  const float* __restrict__ bias,
                  float* __restrict__ out)
{
    extern __shared__ float sm[];
    float* s_A    = sm + OFF_A;
    float* s_E    = sm + OFF_E;
    float* s_ND   = sm + OFF_ND;
    float* s_desc = sm + OFF_DESC;
    int*   s_K0   = (int*)(sm + OFF_K0);
    float* s_mur  = sm + OFF_MUR;
    float* s_isr  = sm + OFF_ISR;

    const int tid = threadIdx.x;
    const int n   = blockIdx.x;
    const float two_pi = 6.2831855f;           // float32(2*pi)
    const float step   = two_pi / 16.0f;

    // ---- prologue: small tables ----
    if (tid < 5) {
        s_mur[tid] = mu_rho[tid * 16];
        float s = sigma_rho[tid * 16];
        s_isr[tid] = 1.0f / (s * s + EPSF);
    }
    float st0 = sigma_theta[0];
    const float ist = 1.0f / (st0 * st0 + EPSF);
    __syncthreads();

    // ---- A build (threads 0..255) and E build (threads 256..383) ----
    if (tid < 256) {
        // A: cols 0..19 = rhoGauss*mask*feat_i, cols 20..24 = rhoGauss*mask
        for (int idx = tid; idx < 640; idx += 256) {
            int r = idx >> 7, v = idx & 127;
            float rv = rho[n * NV + v];
            float m  = mask[n * NV + v];
            float d  = rv - s_mur[r];
            float e  = __expf(-d * d * s_isr[r]) * m;
            s_A[(20 + r) * NV + v] = e;
            float4 f4 = ((const float4*)feat)[n * NV + v];
            s_A[(0 * 5 + r) * NV + v] = e * f4.x;
            s_A[(1 * 5 + r) * NV + v] = e * f4.y;
            s_A[(2 * 5 + r) * NV + v] = e * f4.z;
            s_A[(3 * 5 + r) * NV + v] = e * f4.w;
        }
    } else {
        // E tables: 31 theta-Gaussian values per vertex, 4 exps each
        int v = tid - 256;
        float th = theta[n * NV + v];
        float kf = floorf(th * (16.0f / two_pi));
        int K0 = (int)kf;
        if (K0 > 15) K0 = 15;
        if (K0 < 0)  K0 = 0;
        float u  = th - (float)K0 * step;
        float E0 = __expf(-ist * u * u);
        float q  = __expf(-ist * step * step);
        float q2 = q * q;
        float rr = __expf(-2.0f * ist * u * step);
        float ri = __expf( 2.0f * ist * u * step);
        float* Ep = s_E + v * 33;
        Ep[15] = E0;
        float e = E0, mlt = rr * q;
        #pragma unroll
        for (int j = 1; j <= 15; j++) { e *= mlt; Ep[15 + j] = e; mlt *= q2; }
        e = E0; mlt = ri * q;
        #pragma unroll
        for (int j = 1; j <= 15; j++) { e *= mlt; Ep[15 - j] = e; mlt *= q2; }
        s_K0[v] = K0;
    }
    __syncthreads();

    // ---- ND matmul: (25 x 128) @ (128 x 256) -> s_ND[25][256], FFMA2 ----
    // 10 warps; warp pair owns 5 A-columns (broadcast loads); lane owns 4 kt.
    if (tid < 320) {
        int cg = tid >> 6;            // 0..4, warp-uniform
        int q  = tid & 63;
        int c0 = cg * 5, kt0 = q * 4;
        int kg   = q >> 2;            // shared by all 4 kt of this lane
        int boff = 15 - 4 * (q & 3);  // base = ((kg+K0)&15) + boff

        u64 acc2[5][2];
        #pragma unroll
        for (int c = 0; c < 5; c++) { acc2[c][0] = 0ull; acc2[c][1] = 0ull; }

        #pragma unroll 2
        for (int v = 0; v < NV; v += 4) {
            float a_s[5][4];
            #pragma unroll
            for (int c = 0; c < 5; c++) {
                float4 a4 = *(const float4*)&s_A[(c0 + c) * NV + v];
                a_s[c][0] = a4.x; a_s[c][1] = a4.y;
                a_s[c][2] = a4.z; a_s[c][3] = a4.w;
            }
            #pragma unroll
            for (int jv = 0; jv < 4; jv++) {
                int K0 = s_K0[v + jv];                 // warp-uniform (broadcast)
                const float* Ep = s_E + (v + jv) * 33;
                int base = ((kg + K0) & 15) + boff;
                float t0 = Ep[base];
                float t1 = Ep[base - 1];
                float t2 = Ep[base - 2];
                float t3 = Ep[base - 3];
                u64 tv01 = pk2(t0, t1);
                u64 tv23 = pk2(t2, t3);
                #pragma unroll
                for (int c = 0; c < 5; c++) {
                    u64 aa = pk2(a_s[c][jv], a_s[c][jv]);
                    fma2(acc2[c][0], aa, tv01);
                    fma2(acc2[c][1], aa, tv23);
                }
            }
        }
        #pragma unroll
        for (int c = 0; c < 5; c++) {
            float2 lo = upk2(acc2[c][0]);
            float2 hi = upk2(acc2[c][1]);
            float4 o;
            o.x = lo.x; o.y = lo.y; o.z = hi.x; o.w = hi.y;
            *(float4*)&s_ND[(c0 + c) * 256 + kt0] = o;
        }
    }
    __syncthreads();

    // ---- divide: shared denominators, 1 rcp per (b, k) ----
    if (tid < 320) {
        int kq = tid / 80;               // 0..3
        int b  = tid - kq * 80;          // 0..79
        int r  = b >> 4, t = b & 15;
        const float* Dp = s_ND + (20 + r) * 256 + t;
        float rc[4];
        #pragma unroll
        for (int kk = 0; kk < 4; kk++)
            rc[kk] = __fdividef(1.0f, Dp[(kq * 4 + kk) * 16] + EPSF);
        #pragma unroll
        for (int i = 0; i < 4; i++) {
            const float* Np = s_ND + (i * 5 + r) * 256 + t;
            float4 o;
            o.x = Np[(kq * 4 + 0) * 16] * rc[0];
            o.y = Np[(kq * 4 + 1) * 16] * rc[1];
            o.z = Np[(kq * 4 + 2) * 16] * rc[2];
            o.w = Np[(kq * 4 + 3) * 16] * rc[3];
            *(float4*)&s_desc[(i * NBINS + b) * 20 + kq * 4] = o;
        }
    }
    __syncthreads();

    // ---- conv + max over 16 rotations + relu (320 threads, FFMA2) ----
    // W read directly from gmem (L1/L2 resident, coalesced, 4 loads in flight).
    if (tid < 320) {
        int i = tid / 80;
        int b = tid - i * 80;
        float bi = __ldg(&bias[i * NBINS + b]);
        u64 acc2[8];
        u64 bi2 = pk2(bi, bi);
        #pragma unroll
        for (int j = 0; j < 8; j++) acc2[j] = bi2;

        const float* wcol  = W + i * NBINS * NBINS + b;
        const float* dbase = s_desc + i * NBINS * 20;
        #pragma unroll 4
        for (int bp = 0; bp < NBINS; bp++) {
            float w = __ldg(&wcol[bp * NBINS]);
            u64 ww = pk2(w, w);
            const u64* dq = (const u64*)(dbase + bp * 20);   // 16 k-values, 8B-aligned
            #pragma unroll
            for (int j = 0; j < 8; j++)
                fma2(acc2[j], dq[j], ww);
        }
        float m = -3.4e38f;
        #pragma unroll
        for (int j = 0; j < 8; j++) {
            float2 p = upk2(acc2[j]);
            m = fmaxf(m, fmaxf(p.x, p.y));
        }
        out[(n * 4 + i) * NBINS + b] = fmaxf(m, 0.0f);
    }
}

extern "C" void kernel_launch(void* const* d_in, const int* in_sizes, int n_in,
                              void* d_out, int out_size)
{
    const float* rho         = (const float*)d_in[0];
    const float* theta       = (const float*)d_in[1];
    const float* feat        = (const float*)d_in[2];
    const float* mask        = (const float*)d_in[3];
    const float* mu_rho      = (const float*)d_in[4];
    const float* sigma_rho   = (const float*)d_in[5];
    const float* mu_theta    = (const float*)d_in[6];
    const float* sigma_theta = (const float*)d_in[7];
    const float* W           = (const float*)d_in[8];
    const float* bias        = (const float*)d_in[9];
    float* out = (float*)d_out;

    const size_t smem_bytes = SMEM_FLOATS * sizeof(float);   // 81472
    cudaFuncSetAttribute(masif_kernel,
                         cudaFuncAttributeMaxDynamicSharedMemorySize,
                         (int)smem_bytes);

    masif_kernel<<<4096, 384, smem_bytes>>>(
        rho, theta, feat, mask, mu_rho, sigma_rho, mu_theta, sigma_theta,
        W, bias, out);
}

// round 10
// speedup vs baseline: 2.1606x; 1.1389x over previous
#include <cuda_runtime.h>
#include <cstdint>

// MaSIF geodesic conv, GB300 sm_103a — wavefront-reduction round.
// vs round 8 (299us): ND column tile widened to 9/8/8 over 6 warps (theta-gather
// reuse up 5->~8.3, gather wavefronts -40%); conv desc reads as LDS.128
// (4 instead of 8 loads per bp); block 320, 2 CTAs/SM.
//
// Th[v][k][t] = E_v[((k+K0_v)&15) - t + 15]; E_v built with 4 exps/vertex.
// ND:   (25 x 128) @ (128 x 256) in smem, FFMA2 accumulators.
// conv: desc @ W_i + b_i (W via L1/L2), max over 16 rotations, relu.

#define NV    128
#define NBINS 80
#define EPSF  1e-5f

// smem float offsets (per-CTA total 81472 bytes -> 2 CTAs/SM)
#define OFF_A     0          // 25 x 128
#define OFF_E     3200       // 128 x 33 (pad: conflict-free build + gather)
#define OFF_ND    7424       // 25 x 256
#define OFF_DESC  13824      // 4 x 80 x 20 (stride-20 pad)
#define OFF_K0    20224      // 128 ints
#define OFF_MUR   20352      // 5
#define OFF_ISR   20360      // 5
#define SMEM_FLOATS 20368    // 81472 bytes

typedef unsigned long long u64;

__device__ __forceinline__ u64 pk2(float lo, float hi) {
    u64 r;
    asm("mov.b64 %0, {%1, %2};" : "=l"(r) : "f"(lo), "f"(hi));
    return r;
}
__device__ __forceinline__ void fma2(u64& d, u64 a, u64 b) {
    asm("fma.rn.f32x2 %0, %1, %2, %0;" : "+l"(d) : "l"(a), "l"(b));
}
__device__ __forceinline__ float2 upk2(u64 v) {
    float2 f;
    asm("mov.b64 {%0, %1}, %2;" : "=f"(f.x), "=f"(f.y) : "l"(v));
    return f;
}

// One ND column-group: NC columns starting at C0, lane covers kt0=4q..4q+3.
template<int C0, int NC>
__device__ __forceinline__ void nd_block(const float* __restrict__ s_A,
                                         const float* __restrict__ s_E,
                                         const int* __restrict__ s_K0,
                                         float* __restrict__ s_ND,
                                         int q)
{
    const int kt0  = q * 4;
    const int kg   = q >> 2;            // shared by the lane's 4 kt
    const int boff = 15 - 4 * (q & 3);  // base = ((kg+K0)&15) + boff

    u64 acc2[NC][2];
    #pragma unroll
    for (int c = 0; c < NC; c++) { acc2[c][0] = 0ull; acc2[c][1] = 0ull; }

    #pragma unroll 2
    for (int v = 0; v < NV; v += 4) {
        float4 a4[NC];
        #pragma unroll
        for (int c = 0; c < NC; c++)
            a4[c] = *(const float4*)&s_A[(C0 + c) * NV + v];

        #pragma unroll
        for (int jv = 0; jv < 4; jv++) {
            int K0 = s_K0[v + jv];                 // warp-uniform broadcast
            const float* Ep = s_E + (v + jv) * 33;
            int base = ((kg + K0) & 15) + boff;
            u64 tv01 = pk2(Ep[base],     Ep[base - 1]);
            u64 tv23 = pk2(Ep[base - 2], Ep[base - 3]);
            #pragma unroll
            for (int c = 0; c < NC; c++) {
                float a = (jv == 0) ? a4[c].x : (jv == 1) ? a4[c].y
                        : (jv == 2) ? a4[c].z : a4[c].w;
                u64 aa = pk2(a, a);
                fma2(acc2[c][0], aa, tv01);
                fma2(acc2[c][1], aa, tv23);
            }
        }
    }
    #pragma unroll
    for (int c = 0; c < NC; c++) {
        float2 lo = upk2(acc2[c][0]);
        float2 hi = upk2(acc2[c][1]);
        float4 o;
        o.x = lo.x; o.y = lo.y; o.z = hi.x; o.w = hi.y;
        *(float4*)&s_ND[(C0 + c) * 256 + kt0] = o;
    }
}

__global__ __launch_bounds__(320, 2)
void masif_kernel(const float* __restrict__ rho,
                  const float* __restrict__ theta,
                  const float* __restrict__ feat,
                  const float* __restrict__ mask,
                  const float* __restrict__ mu_rho,
                  const float* __restrict__ sigma_rho,
                  const float* __restrict__ mu_theta,
                  const float* __restrict__ sigma_theta,
                  const float* __restrict__ W,
                  const float* __restrict__ bias,
                  float* __restrict__ out)
{
    extern __shared__ float sm[];
    float* s_A    = sm + OFF_A;
    float* s_E    = sm + OFF_E;
    float* s_ND   = sm + OFF_ND;
    float* s_desc = sm + OFF_DESC;
    int*   s_K0   = (int*)(sm + OFF_K0);
    float* s_mur  = sm + OFF_MUR;
    float* s_isr  = sm + OFF_ISR;

    const int tid = threadIdx.x;
    const int n   = blockIdx.x;
    const float two_pi = 6.2831855f;           // float32(2*pi)
    const float step   = two_pi / 16.0f;

    // ---- prologue: small tables ----
    if (tid < 5) {
        s_mur[tid] = mu_rho[tid * 16];
        float s = sigma_rho[tid * 16];
        s_isr[tid] = 1.0f / (s * s + EPSF);
    }
    float st0 = sigma_theta[0];
    const float ist = 1.0f / (st0 * st0 + EPSF);
    __syncthreads();

    // ---- A build (threads 0..127, one vertex each) ----
    if (tid < 128) {
        int v = tid;
        float rv = rho[n * NV + v];
        float m  = mask[n * NV + v];
        float4 f4 = ((const float4*)feat)[n * NV + v];
        #pragma unroll
        for (int r = 0; r < 5; r++) {
            float d = rv - s_mur[r];
            float e = __expf(-d * d * s_isr[r]) * m;
            s_A[(20 + r) * NV + v] = e;
            s_A[(0 * 5 + r) * NV + v] = e * f4.x;
            s_A[(1 * 5 + r) * NV + v] = e * f4.y;
            s_A[(2 * 5 + r) * NV + v] = e * f4.z;
            s_A[(3 * 5 + r) * NV + v] = e * f4.w;
        }
    } else if (tid < 256) {
        // ---- E tables (threads 128..255): 31 values per vertex, 4 exps ----
        int v = tid - 128;
        float th = theta[n * NV + v];
        float kf = floorf(th * (16.0f / two_pi));
        int K0 = (int)kf;
        if (K0 > 15) K0 = 15;
        if (K0 < 0)  K0 = 0;
        float u  = th - (float)K0 * step;
        float E0 = __expf(-ist * u * u);
        float q  = __expf(-ist * step * step);
        float q2 = q * q;
        float rr = __expf(-2.0f * ist * u * step);
        float ri = __expf( 2.0f * ist * u * step);
        float* Ep = s_E + v * 33;
        Ep[15] = E0;
        float e = E0, mlt = rr * q;
        #pragma unroll
        for (int j = 1; j <= 15; j++) { e *= mlt; Ep[15 + j] = e; mlt *= q2; }
        e = E0; mlt = ri * q;
        #pragma unroll
        for (int j = 1; j <= 15; j++) { e *= mlt; Ep[15 - j] = e; mlt *= q2; }
        s_K0[v] = K0;
    }
    __syncthreads();

    // ---- ND matmul: (25 x 128) @ (128 x 256) -> s_ND[25][256], FFMA2 ----
    // 6 warps: col-groups (9,8,8) x 2 q-warps each; lane owns 4 kt.
    if (tid < 192) {
        int w  = tid >> 5;
        int q  = ((w & 1) << 5) | (tid & 31);   // 0..63
        int cg = w >> 1;                        // 0..2, warp-uniform
        if (cg == 0)      nd_block<0, 9>(s_A, s_E, s_K0, s_ND, q);
        else if (cg == 1) nd_block<9, 8>(s_A, s_E, s_K0, s_ND, q);
        else              nd_block<17, 8>(s_A, s_E, s_K0, s_ND, q);
    }
    __syncthreads();

    // ---- divide: shared denominators, 1 rcp per (b, k) ----
    {
        int kq = tid >> 6 ? (tid / 80) : 0;     // avoid div for tid<64 fastpath (cheap anyway)
        kq = tid / 80;                          // 0..3
        int b  = tid - kq * 80;                 // 0..79
        int r  = b >> 4, t = b & 15;
        const float* Dp = s_ND + (20 + r) * 256 + t;
        float rc[4];
        #pragma unroll
        for (int kk = 0; kk < 4; kk++)
            rc[kk] = __fdividef(1.0f, Dp[(kq * 4 + kk) * 16] + EPSF);
        #pragma unroll
        for (int i = 0; i < 4; i++) {
            const float* Np = s_ND + (i * 5 + r) * 256 + t;
            float4 o;
            o.x = Np[(kq * 4 + 0) * 16] * rc[0];
            o.y = Np[(kq * 4 + 1) * 16] * rc[1];
            o.z = Np[(kq * 4 + 2) * 16] * rc[2];
            o.w = Np[(kq * 4 + 3) * 16] * rc[3];
            *(float4*)&s_desc[(i * NBINS + b) * 20 + kq * 4] = o;
        }
    }
    __syncthreads();

    // ---- conv + max over 16 rotations + relu (320 threads, FFMA2) ----
    // W read directly from gmem (L2 resident, coalesced); desc via LDS.128.
    {
        int i = tid / 80;
        int b = tid - i * 80;
        float bi = __ldg(&bias[i * NBINS + b]);
        u64 acc2[8];
        u64 bi2 = pk2(bi, bi);
        #pragma unroll
        for (int j = 0; j < 8; j++) acc2[j] = bi2;

        const float* wcol  = W + i * NBINS * NBINS + b;
        const float* dbase = s_desc + i * NBINS * 20;
        #pragma unroll 4
        for (int bp = 0; bp < NBINS; bp++) {
            float w = __ldg(&wcol[bp * NBINS]);
            u64 ww = pk2(w, w);
            const float* dp = dbase + bp * 20;           // 16B-aligned
            ulonglong2 q0 = *(const ulonglong2*)(dp);      // k0..k3
            ulonglong2 q1 = *(const ulonglong2*)(dp + 4);  // k4..k7
            ulonglong2 q2 = *(const ulonglong2*)(dp + 8);  // k8..k11
            ulonglong2 q3 = *(const ulonglong2*)(dp + 12); // k12..k15
            fma2(acc2[0], q0.x, ww); fma2(acc2[1], q0.y, ww);
            fma2(acc2[2], q1.x, ww); fma2(acc2[3], q1.y, ww);
            fma2(acc2[4], q2.x, ww); fma2(acc2[5], q2.y, ww);
            fma2(acc2[6], q3.x, ww); fma2(acc2[7], q3.y, ww);
        }
        float m = -3.4e38f;
        #pragma unroll
        for (int j = 0; j < 8; j++) {
            float2 p = upk2(acc2[j]);
            m = fmaxf(m, fmaxf(p.x, p.y));
        }
        out[(n * 4 + i) * NBINS + b] = fmaxf(m, 0.0f);
    }
}

extern "C" void kernel_launch(void* const* d_in, const int* in_sizes, int n_in,
                              void* d_out, int out_size)
{
    const float* rho         = (const float*)d_in[0];
    const float* theta       = (const float*)d_in[1];
    const float* feat        = (const float*)d_in[2];
    const float* mask        = (const float*)d_in[3];
    const float* mu_rho      = (const float*)d_in[4];
    const float* sigma_rho   = (const float*)d_in[5];
    const float* mu_theta    = (const float*)d_in[6];
    const float* sigma_theta = (const float*)d_in[7];
    const float* W           = (const float*)d_in[8];
    const float* bias        = (const float*)d_in[9];
    float* out = (float*)d_out;

    const size_t smem_bytes = SMEM_FLOATS * sizeof(float);   // 81472
    cudaFuncSetAttribute(masif_kernel,
                         cudaFuncAttributeMaxDynamicSharedMemorySize,
                         (int)smem_bytes);

    masif_kernel<<<4096, 320, smem_bytes>>>(
        rho, theta, feat, mask, mu_rho, sigma_rho, mu_theta, sigma_theta,
        W, bias, out);
}

// round 11
// speedup vs baseline: 2.5244x; 1.1684x over previous
#include <cuda_runtime.h>
#include <cstdint>

// MaSIF geodesic conv, GB300 sm_103a — crossbar round 2.
// vs round 9 (263us): ND re-tiled to 4 warps (col-groups 13/12 x 2 kt-halves):
// A-broadcast + gather wavefronts 146->114 per step; conv 2 bins/thread on
// 160 threads (desc broadcasts shared by 2 bins); block 256, 2 CTAs/SM.
//
// Th[v][k][t] = E_v[((k+K0_v)&15) - t + 15]; E_v built with 4 exps/vertex.
// ND:   (25 x 128) @ (128 x 256) in smem, FFMA2 accumulators.
// conv: desc @ W_i + b_i (W via L1/L2), max over 16 rotations, relu.

#define NV    128
#define NBINS 80
#define EPSF  1e-5f

// smem float offsets (per-CTA total 81472 bytes -> 2 CTAs/SM)
#define OFF_A     0          // 25 x 128
#define OFF_E     3200       // 128 x 33 (pad: conflict-free build + gather)
#define OFF_ND    7424       // 25 x 256
#define OFF_DESC  13824      // 4 x 80 x 20 (stride-20 pad)
#define OFF_K0    20224      // 128 ints (16B aligned)
#define OFF_MUR   20352      // 5
#define OFF_ISR   20360      // 5
#define SMEM_FLOATS 20368    // 81472 bytes

typedef unsigned long long u64;

__device__ __forceinline__ u64 pk2(float lo, float hi) {
    u64 r;
    asm("mov.b64 %0, {%1, %2};" : "=l"(r) : "f"(lo), "f"(hi));
    return r;
}
__device__ __forceinline__ void fma2(u64& d, u64 a, u64 b) {
    asm("fma.rn.f32x2 %0, %1, %2, %0;" : "+l"(d) : "l"(a), "l"(b));
}
__device__ __forceinline__ float2 upk2(u64 v) {
    float2 f;
    asm("mov.b64 {%0, %1}, %2;" : "=f"(f.x), "=f"(f.y) : "l"(v));
    return f;
}

// One ND tile: NC columns starting at C0; lane covers kt0 = 4q .. 4q+3.
template<int C0, int NC>
__device__ __forceinline__ void nd_block(const float* __restrict__ s_A,
                                         const float* __restrict__ s_E,
                                         const int* __restrict__ s_K0,
                                         float* __restrict__ s_ND,
                                         int q)
{
    const int kt0  = q * 4;
    const int kg   = q >> 2;            // shared by the lane's 4 kt
    const int boff = 15 - 4 * (q & 3);  // base = ((kg+K0)&15) + boff

    u64 acc2[NC][2];
    #pragma unroll
    for (int c = 0; c < NC; c++) { acc2[c][0] = 0ull; acc2[c][1] = 0ull; }

    #pragma unroll 1
    for (int v = 0; v < NV; v += 4) {
        float4 a4[NC];
        #pragma unroll
        for (int c = 0; c < NC; c++)
            a4[c] = *(const float4*)&s_A[(C0 + c) * NV + v];

        int4 k4 = *(const int4*)&s_K0[v];          // warp-uniform broadcast
        int kvals[4] = {k4.x, k4.y, k4.z, k4.w};

        #pragma unroll
        for (int jv = 0; jv < 4; jv++) {
            const float* Ep = s_E + (v + jv) * 33;
            int base = ((kg + kvals[jv]) & 15) + boff;
            u64 tv01 = pk2(Ep[base],     Ep[base - 1]);
            u64 tv23 = pk2(Ep[base - 2], Ep[base - 3]);
            #pragma unroll
            for (int c = 0; c < NC; c++) {
                float a = (jv == 0) ? a4[c].x : (jv == 1) ? a4[c].y
                        : (jv == 2) ? a4[c].z : a4[c].w;
                u64 aa = pk2(a, a);
                fma2(acc2[c][0], aa, tv01);
                fma2(acc2[c][1], aa, tv23);
            }
        }
    }
    #pragma unroll
    for (int c = 0; c < NC; c++) {
        float2 lo = upk2(acc2[c][0]);
        float2 hi = upk2(acc2[c][1]);
        float4 o;
        o.x = lo.x; o.y = lo.y; o.z = hi.x; o.w = hi.y;
        *(float4*)&s_ND[(C0 + c) * 256 + kt0] = o;
    }
}

__global__ __launch_bounds__(256, 2)
void masif_kernel(const float* __restrict__ rho,
                  const float* __restrict__ theta,
                  const float* __restrict__ feat,
                  const float* __restrict__ mask,
                  const float* __restrict__ mu_rho,
                  const float* __restrict__ sigma_rho,
                  const float* __restrict__ mu_theta,
                  const float* __restrict__ sigma_theta,
                  const float* __restrict__ W,
                  const float* __restrict__ bias,
                  float* __restrict__ out)
{
    extern __shared__ float sm[];
    float* s_A    = sm + OFF_A;
    float* s_E    = sm + OFF_E;
    float* s_ND   = sm + OFF_ND;
    float* s_desc = sm + OFF_DESC;
    int*   s_K0   = (int*)(sm + OFF_K0);
    float* s_mur  = sm + OFF_MUR;
    float* s_isr  = sm + OFF_ISR;

    const int tid = threadIdx.x;
    const int n   = blockIdx.x;
    const float two_pi = 6.2831855f;           // float32(2*pi)
    const float step   = two_pi / 16.0f;

    // ---- prologue: small tables ----
    if (tid < 5) {
        s_mur[tid] = mu_rho[tid * 16];
        float s = sigma_rho[tid * 16];
        s_isr[tid] = 1.0f / (s * s + EPSF);
    }
    float st0 = sigma_theta[0];
    const float ist = 1.0f / (st0 * st0 + EPSF);
    __syncthreads();

    // ---- A build (threads 0..127) and E build (threads 128..255) ----
    if (tid < 128) {
        int v = tid;
        float rv = rho[n * NV + v];
        float m  = mask[n * NV + v];
        float4 f4 = ((const float4*)feat)[n * NV + v];
        #pragma unroll
        for (int r = 0; r < 5; r++) {
            float d = rv - s_mur[r];
            float e = __expf(-d * d * s_isr[r]) * m;
            s_A[(20 + r) * NV + v] = e;
            s_A[(0 * 5 + r) * NV + v] = e * f4.x;
            s_A[(1 * 5 + r) * NV + v] = e * f4.y;
            s_A[(2 * 5 + r) * NV + v] = e * f4.z;
            s_A[(3 * 5 + r) * NV + v] = e * f4.w;
        }
    } else {
        // E tables: 31 theta-Gaussian values per vertex, 4 exps each
        int v = tid - 128;
        float th = theta[n * NV + v];
        float kf = floorf(th * (16.0f / two_pi));
        int K0 = (int)kf;
        if (K0 > 15) K0 = 15;
        if (K0 < 0)  K0 = 0;
        float u  = th - (float)K0 * step;
        float E0 = __expf(-ist * u * u);
        float q  = __expf(-ist * step * step);
        float q2 = q * q;
        float rr = __expf(-2.0f * ist * u * step);
        float ri = __expf( 2.0f * ist * u * step);
        float* Ep = s_E + v * 33;
        Ep[15] = E0;
        float e = E0, mlt = rr * q;
        #pragma unroll
        for (int j = 1; j <= 15; j++) { e *= mlt; Ep[15 + j] = e; mlt *= q2; }
        e = E0; mlt = ri * q;
        #pragma unroll
        for (int j = 1; j <= 15; j++) { e *= mlt; Ep[15 - j] = e; mlt *= q2; }
        s_K0[v] = K0;
    }
    __syncthreads();

    // ---- ND matmul: (25 x 128) @ (128 x 256) -> s_ND[25][256], FFMA2 ----
    // 4 warps: col-groups (13,12) x 2 kt-halves; lane owns 4 kt.
    if (tid < 128) {
        int w  = tid >> 5;
        int q  = ((w & 1) << 5) | (tid & 31);   // 0..63
        if ((w >> 1) == 0) nd_block<0, 13>(s_A, s_E, s_K0, s_ND, q);
        else               nd_block<13, 12>(s_A, s_E, s_K0, s_ND, q);
    }
    __syncthreads();

    // ---- divide: shared denominators, 1 rcp per (b, k); 320 items / 256 thr ----
    for (int idx = tid; idx < 320; idx += 256) {
        int kq = idx / 80;               // 0..3
        int b  = idx - kq * 80;          // 0..79
        int r  = b >> 4, t = b & 15;
        const float* Dp = s_ND + (20 + r) * 256 + t;
        float rc[4];
        #pragma unroll
        for (int kk = 0; kk < 4; kk++)
            rc[kk] = __fdividef(1.0f, Dp[(kq * 4 + kk) * 16] + EPSF);
        #pragma unroll
        for (int i = 0; i < 4; i++) {
            const float* Np = s_ND + (i * 5 + r) * 256 + t;
            float4 o;
            o.x = Np[(kq * 4 + 0) * 16] * rc[0];
            o.y = Np[(kq * 4 + 1) * 16] * rc[1];
            o.z = Np[(kq * 4 + 2) * 16] * rc[2];
            o.w = Np[(kq * 4 + 3) * 16] * rc[3];
            *(float4*)&s_desc[(i * NBINS + b) * 20 + kq * 4] = o;
        }
    }
    __syncthreads();

    // ---- conv + max over 16 rot + relu: 160 threads, 2 bins/thread ----
    // W via L2 (coalesced float2); desc LDS.128 broadcasts feed both bins.
    if (tid < 160) {
        int i  = tid / 40;
        int j  = tid - i * 40;
        int b0 = j * 2;

        float2 bv = *(const float2*)&bias[i * NBINS + b0];
        u64 accA[8], accB[8];
        u64 bA = pk2(bv.x, bv.x), bB = pk2(bv.y, bv.y);
        #pragma unroll
        for (int jj = 0; jj < 8; jj++) { accA[jj] = bA; accB[jj] = bB; }

        const float* wcol  = W + i * NBINS * NBINS + b0;
        const float* dbase = s_desc + i * NBINS * 20;
        #pragma unroll 4
        for (int bp = 0; bp < NBINS; bp++) {
            float2 wv = *(const float2*)&wcol[bp * NBINS];
            u64 wa = pk2(wv.x, wv.x);
            u64 wb = pk2(wv.y, wv.y);
            const float* dp = dbase + bp * 20;             // 16B-aligned
            ulonglong2 q0 = *(const ulonglong2*)(dp);        // k0..k3
            ulonglong2 q1 = *(const ulonglong2*)(dp + 4);    // k4..k7
            ulonglong2 q2 = *(const ulonglong2*)(dp + 8);    // k8..k11
            ulonglong2 q3 = *(const ulonglong2*)(dp + 12);   // k12..k15
            fma2(accA[0], q0.x, wa); fma2(accB[0], q0.x, wb);
            fma2(accA[1], q0.y, wa); fma2(accB[1], q0.y, wb);
            fma2(accA[2], q1.x, wa); fma2(accB[2], q1.x, wb);
            fma2(accA[3], q1.y, wa); fma2(accB[3], q1.y, wb);
            fma2(accA[4], q2.x, wa); fma2(accB[4], q2.x, wb);
            fma2(accA[5], q2.y, wa); fma2(accB[5], q2.y, wb);
            fma2(accA[6], q3.x, wa); fma2(accB[6], q3.x, wb);
            fma2(accA[7], q3.y, wa); fma2(accB[7], q3.y, wb);
        }
        float mA = -3.4e38f, mB = -3.4e38f;
        #pragma unroll
        for (int jj = 0; jj < 8; jj++) {
            float2 pa = upk2(accA[jj]);
            float2 pb = upk2(accB[jj]);
            mA = fmaxf(mA, fmaxf(pa.x, pa.y));
            mB = fmaxf(mB, fmaxf(pb.x, pb.y));
        }
        float2 o;
        o.x = fmaxf(mA, 0.0f);
        o.y = fmaxf(mB, 0.0f);
        *(float2*)&out[(n * 4 + i) * NBINS + b0] = o;
    }
}

extern "C" void kernel_launch(void* const* d_in, const int* in_sizes, int n_in,
                              void* d_out, int out_size)
{
    const float* rho         = (const float*)d_in[0];
    const float* theta       = (const float*)d_in[1];
    const float* feat        = (const float*)d_in[2];
    const float* mask        = (const float*)d_in[3];
    const float* mu_rho      = (const float*)d_in[4];
    const float* sigma_rho   = (const float*)d_in[5];
    const float* mu_theta    = (const float*)d_in[6];
    const float* sigma_theta = (const float*)d_in[7];
    const float* W           = (const float*)d_in[8];
    const float* bias        = (const float*)d_in[9];
    float* out = (float*)d_out;

    const size_t smem_bytes = SMEM_FLOATS * sizeof(float);   // 81472
    cudaFuncSetAttribute(masif_kernel,
                         cudaFuncAttributeMaxDynamicSharedMemorySize,
                         (int)smem_bytes);

    masif_kernel<<<4096, 256, smem_bytes>>>(
        rho, theta, feat, mask, mu_rho, sigma_rho, mu_theta, sigma_theta,
        W, bias, out);
}

// round 12
// speedup vs baseline: 2.6890x; 1.0652x over previous
#include <cuda_runtime.h>
#include <cstdint>

// MaSIF geodesic conv, GB300 sm_103a — occupancy round 2 (3 CTAs/SM).
// vs round 10 (225us): ND re-tiled to 8 warps, col-groups (7,6,6,6) x 2
// kt-halves -> accumulator regs 104->28, target <=85 regs; desc aliased onto
// dead A/E smem -> 55.9KB/CTA; __launch_bounds__(256,3) -> 24 resident warps.
//
// Th[v][k][t] = E_v[((k+K0_v)&15) - t + 15]; E_v built with 4 exps/vertex.
// ND:   (25 x 128) @ (128 x 256) in smem, FFMA2 accumulators.
// conv: desc @ W_i + b_i (W via L1/L2), max over 16 rotations, relu.

#define NV    128
#define NBINS 80
#define EPSF  1e-5f

// smem float offsets (per-CTA total 55872 bytes -> 3 CTAs/SM)
#define OFF_A     0          // 25 x 128   (dead after ND)
#define OFF_E     3200       // 128 x 33   (dead after ND)
#define OFF_DESC  0          // 4 x 80 x 20 — ALIASES A/E (written in divide)
#define OFF_ND    7424       // 25 x 256
#define OFF_K0    13824      // 128 ints (16B aligned)
#define OFF_MUR   13952      // 5
#define OFF_ISR   13960      // 5
#define SMEM_FLOATS 13968    // 55872 bytes

typedef unsigned long long u64;

__device__ __forceinline__ u64 pk2(float lo, float hi) {
    u64 r;
    asm("mov.b64 %0, {%1, %2};" : "=l"(r) : "f"(lo), "f"(hi));
    return r;
}
__device__ __forceinline__ void fma2(u64& d, u64 a, u64 b) {
    asm("fma.rn.f32x2 %0, %1, %2, %0;" : "+l"(d) : "l"(a), "l"(b));
}
__device__ __forceinline__ float2 upk2(u64 v) {
    float2 f;
    asm("mov.b64 {%0, %1}, %2;" : "=f"(f.x), "=f"(f.y) : "l"(v));
    return f;
}

// One ND tile: NC columns starting at C0; lane covers kt0 = 4q .. 4q+3.
template<int C0, int NC>
__device__ __forceinline__ void nd_block(const float* __restrict__ s_A,
                                         const float* __restrict__ s_E,
                                         const int* __restrict__ s_K0,
                                         float* __restrict__ s_ND,
                                         int q)
{
    const int kt0  = q * 4;
    const int kg   = q >> 2;            // shared by the lane's 4 kt
    const int boff = 15 - 4 * (q & 3);  // base = ((kg+K0)&15) + boff

    u64 acc2[NC][2];
    #pragma unroll
    for (int c = 0; c < NC; c++) { acc2[c][0] = 0ull; acc2[c][1] = 0ull; }

    #pragma unroll 1
    for (int v = 0; v < NV; v += 4) {
        float4 a4[NC];
        #pragma unroll
        for (int c = 0; c < NC; c++)
            a4[c] = *(const float4*)&s_A[(C0 + c) * NV + v];

        int4 k4 = *(const int4*)&s_K0[v];          // warp-uniform broadcast
        int kvals[4] = {k4.x, k4.y, k4.z, k4.w};

        #pragma unroll
        for (int jv = 0; jv < 4; jv++) {
            const float* Ep = s_E + (v + jv) * 33;
            int base = ((kg + kvals[jv]) & 15) + boff;
            u64 tv01 = pk2(Ep[base],     Ep[base - 1]);
            u64 tv23 = pk2(Ep[base - 2], Ep[base - 3]);
            #pragma unroll
            for (int c = 0; c < NC; c++) {
                float a = (jv == 0) ? a4[c].x : (jv == 1) ? a4[c].y
                        : (jv == 2) ? a4[c].z : a4[c].w;
                u64 aa = pk2(a, a);
                fma2(acc2[c][0], aa, tv01);
                fma2(acc2[c][1], aa, tv23);
            }
        }
    }
    #pragma unroll
    for (int c = 0; c < NC; c++) {
        float2 lo = upk2(acc2[c][0]);
        float2 hi = upk2(acc2[c][1]);
        float4 o;
        o.x = lo.x; o.y = lo.y; o.z = hi.x; o.w = hi.y;
        *(float4*)&s_ND[(C0 + c) * 256 + kt0] = o;
    }
}

__global__ __launch_bounds__(256, 3)
void masif_kernel(const float* __restrict__ rho,
                  const float* __restrict__ theta,
                  const float* __restrict__ feat,
                  const float* __restrict__ mask,
                  const float* __restrict__ mu_rho,
                  const float* __restrict__ sigma_rho,
                  const float* __restrict__ mu_theta,
                  const float* __restrict__ sigma_theta,
                  const float* __restrict__ W,
                  const float* __restrict__ bias,
                  float* __restrict__ out)
{
    extern __shared__ float sm[];
    float* s_A    = sm + OFF_A;
    float* s_E    = sm + OFF_E;
    float* s_ND   = sm + OFF_ND;
    float* s_desc = sm + OFF_DESC;   // aliases A/E (safe: written after ND)
    int*   s_K0   = (int*)(sm + OFF_K0);
    float* s_mur  = sm + OFF_MUR;
    float* s_isr  = sm + OFF_ISR;

    const int tid = threadIdx.x;
    const int n   = blockIdx.x;
    const float two_pi = 6.2831855f;           // float32(2*pi)
    const float step   = two_pi / 16.0f;

    // ---- prologue: small tables ----
    if (tid < 5) {
        s_mur[tid] = mu_rho[tid * 16];
        float s = sigma_rho[tid * 16];
        s_isr[tid] = 1.0f / (s * s + EPSF);
    }
    float st0 = sigma_theta[0];
    const float ist = 1.0f / (st0 * st0 + EPSF);
    __syncthreads();

    // ---- A build (threads 0..127) and E build (threads 128..255) ----
    if (tid < 128) {
        int v = tid;
        float rv = rho[n * NV + v];
        float m  = mask[n * NV + v];
        float4 f4 = ((const float4*)feat)[n * NV + v];
        #pragma unroll
        for (int r = 0; r < 5; r++) {
            float d = rv - s_mur[r];
            float e = __expf(-d * d * s_isr[r]) * m;
            s_A[(20 + r) * NV + v] = e;
            s_A[(0 * 5 + r) * NV + v] = e * f4.x;
            s_A[(1 * 5 + r) * NV + v] = e * f4.y;
            s_A[(2 * 5 + r) * NV + v] = e * f4.z;
            s_A[(3 * 5 + r) * NV + v] = e * f4.w;
        }
    } else {
        // E tables: 31 theta-Gaussian values per vertex, 4 exps each
        int v = tid - 128;
        float th = theta[n * NV + v];
        float kf = floorf(th * (16.0f / two_pi));
        int K0 = (int)kf;
        if (K0 > 15) K0 = 15;
        if (K0 < 0)  K0 = 0;
        float u  = th - (float)K0 * step;
        float E0 = __expf(-ist * u * u);
        float q  = __expf(-ist * step * step);
        float q2 = q * q;
        float rr = __expf(-2.0f * ist * u * step);
        float ri = __expf( 2.0f * ist * u * step);
        float* Ep = s_E + v * 33;
        Ep[15] = E0;
        float e = E0, mlt = rr * q;
        #pragma unroll
        for (int j = 1; j <= 15; j++) { e *= mlt; Ep[15 + j] = e; mlt *= q2; }
        e = E0; mlt = ri * q;
        #pragma unroll
        for (int j = 1; j <= 15; j++) { e *= mlt; Ep[15 - j] = e; mlt *= q2; }
        s_K0[v] = K0;
    }
    __syncthreads();

    // ---- ND matmul: (25 x 128) @ (128 x 256) -> s_ND[25][256], FFMA2 ----
    // 8 warps: col-groups (7,6,6,6) x 2 kt-halves; lane owns 4 kt.
    {
        int w  = tid >> 5;
        int q  = ((w & 1) << 5) | (tid & 31);   // 0..63
        int cg = w >> 1;                        // 0..3, warp-uniform
        if (cg == 0)      nd_block<0, 7>(s_A, s_E, s_K0, s_ND, q);
        else if (cg == 1) nd_block<7, 6>(s_A, s_E, s_K0, s_ND, q);
        else if (cg == 2) nd_block<13, 6>(s_A, s_E, s_K0, s_ND, q);
        else              nd_block<19, 6>(s_A, s_E, s_K0, s_ND, q);
    }
    __syncthreads();

    // ---- divide: shared denominators, 1 rcp per (b, k); 320 items / 256 thr ----
    // (writes s_desc, which aliases the now-dead A/E region)
    for (int idx = tid; idx < 320; idx += 256) {
        int kq = idx / 80;               // 0..3
        int b  = idx - kq * 80;          // 0..79
        int r  = b >> 4, t = b & 15;
        const float* Dp = s_ND + (20 + r) * 256 + t;
        float rc[4];
        #pragma unroll
        for (int kk = 0; kk < 4; kk++)
            rc[kk] = __fdividef(1.0f, Dp[(kq * 4 + kk) * 16] + EPSF);
        #pragma unroll
        for (int i = 0; i < 4; i++) {
            const float* Np = s_ND + (i * 5 + r) * 256 + t;
            float4 o;
            o.x = Np[(kq * 4 + 0) * 16] * rc[0];
            o.y = Np[(kq * 4 + 1) * 16] * rc[1];
            o.z = Np[(kq * 4 + 2) * 16] * rc[2];
            o.w = Np[(kq * 4 + 3) * 16] * rc[3];
            *(float4*)&s_desc[(i * NBINS + b) * 20 + kq * 4] = o;
        }
    }
    __syncthreads();

    // ---- conv + max over 16 rot + relu: 160 threads, 2 bins/thread ----
    // W via L2 (coalesced float2); desc LDS.128 broadcasts feed both bins.
    if (tid < 160) {
        int i  = tid / 40;
        int j  = tid - i * 40;
        int b0 = j * 2;

        float2 bv = *(const float2*)&bias[i * NBINS + b0];
        u64 accA[8], accB[8];
        u64 bA = pk2(bv.x, bv.x), bB = pk2(bv.y, bv.y);
        #pragma unroll
        for (int jj = 0; jj < 8; jj++) { accA[jj] = bA; accB[jj] = bB; }

        const float* wcol  = W + i * NBINS * NBINS + b0;
        const float* dbase = s_desc + i * NBINS * 20;
        #pragma unroll 4
        for (int bp = 0; bp < NBINS; bp++) {
            float2 wv = *(const float2*)&wcol[bp * NBINS];
            u64 wa = pk2(wv.x, wv.x);
            u64 wb = pk2(wv.y, wv.y);
            const float* dp = dbase + bp * 20;             // 16B-aligned
            ulonglong2 q0 = *(const ulonglong2*)(dp);        // k0..k3
            ulonglong2 q1 = *(const ulonglong2*)(dp + 4);    // k4..k7
            ulonglong2 q2 = *(const ulonglong2*)(dp + 8);    // k8..k11
            ulonglong2 q3 = *(const ulonglong2*)(dp + 12);   // k12..k15
            fma2(accA[0], q0.x, wa); fma2(accB[0], q0.x, wb);
            fma2(accA[1], q0.y, wa); fma2(accB[1], q0.y, wb);
            fma2(accA[2], q1.x, wa); fma2(accB[2], q1.x, wb);
            fma2(accA[3], q1.y, wa); fma2(accB[3], q1.y, wb);
            fma2(accA[4], q2.x, wa); fma2(accB[4], q2.x, wb);
            fma2(accA[5], q2.y, wa); fma2(accB[5], q2.y, wb);
            fma2(accA[6], q3.x, wa); fma2(accB[6], q3.x, wb);
            fma2(accA[7], q3.y, wa); fma2(accB[7], q3.y, wb);
        }
        float mA = -3.4e38f, mB = -3.4e38f;
        #pragma unroll
        for (int jj = 0; jj < 8; jj++) {
            float2 pa = upk2(accA[jj]);
            float2 pb = upk2(accB[jj]);
            mA = fmaxf(mA, fmaxf(pa.x, pa.y));
            mB = fmaxf(mB, fmaxf(pb.x, pb.y));
        }
        float2 o;
        o.x = fmaxf(mA, 0.0f);
        o.y = fmaxf(mB, 0.0f);
        *(float2*)&out[(n * 4 + i) * NBINS + b0] = o;
    }
}

extern "C" void kernel_launch(void* const* d_in, const int* in_sizes, int n_in,
                              void* d_out, int out_size)
{
    const float* rho         = (const float*)d_in[0];
    const float* theta       = (const float*)d_in[1];
    const float* feat        = (const float*)d_in[2];
    const float* mask        = (const float*)d_in[3];
    const float* mu_rho      = (const float*)d_in[4];
    const float* sigma_rho   = (const float*)d_in[5];
    const float* mu_theta    = (const float*)d_in[6];
    const float* sigma_theta = (const float*)d_in[7];
    const float* W           = (const float*)d_in[8];
    const float* bias        = (const float*)d_in[9];
    float* out = (float*)d_out;

    const size_t smem_bytes = SMEM_FLOATS * sizeof(float);   // 55872
    cudaFuncSetAttribute(masif_kernel,
                         cudaFuncAttributeMaxDynamicSharedMemorySize,
                         (int)smem_bytes);

    masif_kernel<<<4096, 256, smem_bytes>>>(
        rho, theta, feat, mask, mu_rho, sigma_rho, mu_theta, sigma_theta,
        W, bias, out);
}